// round 10
// baseline (speedup 1.0000x reference)
#include <cuda_runtime.h>
#include <cuda_fp16.h>
#include <math.h>

#define NN   100000
#define NE   3200000
#define NV   (NE / 8)          // 8-edge vectors
#define NBLK 592               // 4 blocks/SM * 148 SMs  (<= resident capacity)
#define NTHR 256
#define NTOT (NBLK * NTHR)

// Scratch (static device globals — no allocs anywhere)
__device__ int      g_src[NE];   // int64-fallback only
__device__ int      g_dst[NE];   // int64-fallback only
__device__ __half   g_w16[NE];   // fp16 weight cache (6.4MB)
__device__ float    g_deg[NN];
__device__ __half   g_p1[NN];    // half(dinv * x)
__device__ float    g_acc1[NN];
__device__ __half   g_gd[NN];    // half(dinv * (g1-g0))
__device__ float    g_acc2[NN];
__device__ unsigned g_cnt[8];    // grid-barrier counters (zeroed each run)
__device__ unsigned g_hi_or;     // 0 => int64 edge_index

__device__ __forceinline__ int clampn(int v) { return min(max(v, 0), NN - 1); }

// ---- software grid barrier: all NBLK blocks are resident by construction ----
__device__ __forceinline__ void grid_sync(int slot) {
    __threadfence();                       // release this thread's prior writes
    __syncthreads();
    if (threadIdx.x == 0) {
        atomicAdd(&g_cnt[slot], 1u);
        while (*(volatile unsigned*)&g_cnt[slot] < NBLK) __nanosleep(64);
    }
    __syncthreads();
    __threadfence();                       // acquire remote writes
}

// --------------- reset: barrier counters, node init, dtype probe ------------
__global__ void k_reset(const unsigned int* __restrict__ ei32) {
    int n = blockIdx.x * blockDim.x + threadIdx.x;
    if (n < 8) g_cnt[n] = 0u;
    if (n == 8) g_hi_or = 0u;
    if (n < NN) {
        g_deg[n]  = 1.0f;     // self-loop weight
        g_acc1[n] = 0.0f;
    }
    if (blockIdx.x == 0) {    // sample 2048 odd words (0 iff int64 high-halves)
        unsigned v = 0u;
        #pragma unroll
        for (int k = 0; k < 8; k++) v |= ei32[2 * (threadIdx.x * 8 + k) + 1];
        #pragma unroll
        for (int off = 16; off > 0; off >>= 1)
            v |= __shfl_xor_sync(0xFFFFFFFFu, v, off);
        if ((threadIdx.x & 31) == 0 && v) atomicOr(&g_hi_or, v);
    }
}

// --------------------------- the whole GCN in one kernel --------------------
__global__ void __launch_bounds__(NTHR, 4)
k_fused(const void* __restrict__ eiv, const float* __restrict__ w,
        const float* __restrict__ x,  const float* __restrict__ W1,
        const float* __restrict__ b1, const float* __restrict__ W2,
        const float* __restrict__ b2, float2* __restrict__ out) {
    const int gid   = blockIdx.x * NTHR + threadIdx.x;
    const bool i64  = (g_hi_or == 0u);
    const int* sp   = i64 ? g_src : (const int*)eiv;
    const int* dp   = i64 ? g_dst : (const int*)eiv + NE;

    // ---- phase 1: degree REDs + fp16 weight cache (+ narrowing if int64) ----
    if (!i64) {
        for (int v = gid; v < NV; v += NTOT) {
            int e = v * 8;
            float4 wa = __ldcs((const float4*)(w + e));
            float4 wb = __ldcs((const float4*)(w + e + 4));
            __half2 h0 = __floats2half2_rn(wa.x, wa.y);
            __half2 h1 = __floats2half2_rn(wa.z, wa.w);
            __half2 h2 = __floats2half2_rn(wb.x, wb.y);
            __half2 h3 = __floats2half2_rn(wb.z, wb.w);
            *(uint4*)(g_w16 + e) = make_uint4(*(unsigned*)&h0, *(unsigned*)&h1,
                                              *(unsigned*)&h2, *(unsigned*)&h3);
            int4 da = __ldcs((const int4*)(dp + e));
            int4 db = __ldcs((const int4*)(dp + e + 4));
            atomicAdd(&g_deg[clampn(da.x)], wa.x);
            atomicAdd(&g_deg[clampn(da.y)], wa.y);
            atomicAdd(&g_deg[clampn(da.z)], wa.z);
            atomicAdd(&g_deg[clampn(da.w)], wa.w);
            atomicAdd(&g_deg[clampn(db.x)], wb.x);
            atomicAdd(&g_deg[clampn(db.y)], wb.y);
            atomicAdd(&g_deg[clampn(db.z)], wb.z);
            atomicAdd(&g_deg[clampn(db.w)], wb.w);
        }
    } else {
        for (int e0 = gid * 8; e0 < NE; e0 += NTOT * 8) {
            const long long* ei = (const long long*)eiv;
            #pragma unroll
            for (int k = 0; k < 8; k++) {
                int e = e0 + k;
                int s = clampn((int)ei[e]);
                int d = clampn((int)ei[NE + e]);
                float wk = w[e];
                g_src[e] = s;  g_dst[e] = d;
                g_w16[e] = __float2half_rn(wk);
                atomicAdd(&g_deg[d], wk);
            }
        }
    }
    grid_sync(0);

    // ---- phase 2: dinv + scaled feature (register-cached for this node) ----
    float my_di = 0.0f;
    if (gid < NN) {
        float d  = g_deg[gid];
        my_di = (d > 0.0f) ? rsqrtf(d) : 0.0f;
        g_p1[gid] = __float2half_rn(my_di * x[gid]);
    }
    grid_sync(1);

    // ---- phase 3: layer-1 aggregation  acc1[d] += w * p1[s] ----------------
    for (int v = gid; v < NV; v += NTOT) {
        int e = v * 8;
        int4  sa = __ldcs((const int4*)(sp + e));
        int4  sb = __ldcs((const int4*)(sp + e + 4));
        int4  da = __ldcs((const int4*)(dp + e));
        int4  db = __ldcs((const int4*)(dp + e + 4));
        uint4 wp = __ldcs((const uint4*)(g_w16 + e));
        float2 w01 = __half22float2(*(__half2*)&wp.x);
        float2 w23 = __half22float2(*(__half2*)&wp.y);
        float2 w45 = __half22float2(*(__half2*)&wp.z);
        float2 w67 = __half22float2(*(__half2*)&wp.w);
        float p0 = __half2float(g_p1[clampn(sa.x)]);
        float p1 = __half2float(g_p1[clampn(sa.y)]);
        float p2 = __half2float(g_p1[clampn(sa.z)]);
        float p3 = __half2float(g_p1[clampn(sa.w)]);
        float p4 = __half2float(g_p1[clampn(sb.x)]);
        float p5 = __half2float(g_p1[clampn(sb.y)]);
        float p6 = __half2float(g_p1[clampn(sb.z)]);
        float p7 = __half2float(g_p1[clampn(sb.w)]);
        atomicAdd(&g_acc1[clampn(da.x)], w01.x * p0);
        atomicAdd(&g_acc1[clampn(da.y)], w01.y * p1);
        atomicAdd(&g_acc1[clampn(da.z)], w23.x * p2);
        atomicAdd(&g_acc1[clampn(da.w)], w23.y * p3);
        atomicAdd(&g_acc1[clampn(db.x)], w45.x * p4);
        atomicAdd(&g_acc1[clampn(db.y)], w45.y * p5);
        atomicAdd(&g_acc1[clampn(db.z)], w67.x * p6);
        atomicAdd(&g_acc1[clampn(db.w)], w67.y * p7);
    }
    grid_sync(2);

    // ---- phase 4: dense W1/b1/relu/W2 delta, seed self term ----------------
    if (gid < NN) {
        float sv = my_di * (g_acc1[gid] + my_di * x[gid]);
        float g0 = 0.0f, g1 = 0.0f;
        #pragma unroll
        for (int j = 0; j < 16; j++) {
            float h = fmaxf(fmaf(sv, __ldg(&W1[j]), __ldg(&b1[j])), 0.0f);
            g0 = fmaf(h, __ldg(&W2[2 * j    ]), g0);
            g1 = fmaf(h, __ldg(&W2[2 * j + 1]), g1);
        }
        float gd = my_di * (g1 - g0);
        g_gd[gid]   = __float2half_rn(gd);
        g_acc2[gid] = gd;              // self-loop seed
    }
    grid_sync(3);

    // ---- phase 5: layer-2 aggregation (scalar)  acc2[d] += w * gd[s] -------
    for (int v = gid; v < NV; v += NTOT) {
        int e = v * 8;
        int4  sa = __ldcs((const int4*)(sp + e));
        int4  sb = __ldcs((const int4*)(sp + e + 4));
        int4  da = __ldcs((const int4*)(dp + e));
        int4  db = __ldcs((const int4*)(dp + e + 4));
        uint4 wp = __ldcs((const uint4*)(g_w16 + e));
        float2 w01 = __half22float2(*(__half2*)&wp.x);
        float2 w23 = __half22float2(*(__half2*)&wp.y);
        float2 w45 = __half22float2(*(__half2*)&wp.z);
        float2 w67 = __half22float2(*(__half2*)&wp.w);
        float v0 = __half2float(g_gd[clampn(sa.x)]);
        float v1 = __half2float(g_gd[clampn(sa.y)]);
        float v2 = __half2float(g_gd[clampn(sa.z)]);
        float v3 = __half2float(g_gd[clampn(sa.w)]);
        float v4 = __half2float(g_gd[clampn(sb.x)]);
        float v5 = __half2float(g_gd[clampn(sb.y)]);
        float v6 = __half2float(g_gd[clampn(sb.z)]);
        float v7 = __half2float(g_gd[clampn(sb.w)]);
        atomicAdd(&g_acc2[clampn(da.x)], w01.x * v0);
        atomicAdd(&g_acc2[clampn(da.y)], w01.y * v1);
        atomicAdd(&g_acc2[clampn(da.z)], w23.x * v2);
        atomicAdd(&g_acc2[clampn(da.w)], w23.y * v3);
        atomicAdd(&g_acc2[clampn(db.x)], w45.x * v4);
        atomicAdd(&g_acc2[clampn(db.y)], w45.y * v5);
        atomicAdd(&g_acc2[clampn(db.z)], w67.x * v6);
        atomicAdd(&g_acc2[clampn(db.w)], w67.y * v7);
    }
    grid_sync(4);

    // ---- phase 6: delta -> 2-way log_softmax -------------------------------
    if (gid < NN) {
        float vdl = my_di * g_acc2[gid] + (__ldg(&b2[1]) - __ldg(&b2[0]));
        float o0 = (vdl > 0.0f) ? (-vdl - log1pf(expf(-vdl)))
                                : (-log1pf(expf(vdl)));
        out[gid] = make_float2(o0, o0 + vdl);
    }
}

extern "C" void kernel_launch(void* const* d_in, const int* in_sizes, int n_in,
                              void* d_out, int out_size) {
    const float* x = 0; const void* ei = 0; const float* w = 0;
    const float* W1 = 0; const float* b1 = 0; const float* W2 = 0; const float* b2 = 0;
    for (int i = 0; i < n_in; i++) {
        int sz = in_sizes[i];
        if      (sz == NN)     x  = (const float*)d_in[i];
        else if (sz == 2 * NE) ei = d_in[i];
        else if (sz == NE)     w  = (const float*)d_in[i];
        else if (sz == 32)     W2 = (const float*)d_in[i];
        else if (sz == 2)      b2 = (const float*)d_in[i];
        else if (sz == 16) {
            if (!W1) W1 = (const float*)d_in[i];
            else     b1 = (const float*)d_in[i];
        }
    }
    const int GN = (NN + NTHR - 1) / NTHR;
    k_reset<<<GN,   NTHR>>>((const unsigned int*)ei);
    k_fused<<<NBLK, NTHR>>>(ei, w, x, W1, b1, W2, b2, (float2*)d_out);
}

// round 11
// speedup vs baseline: 1.2819x; 1.2819x over previous
#include <cuda_runtime.h>
#include <cuda_fp16.h>
#include <math.h>

#define NN 100000
#define NE 3200000

// Scratch (static device globals — no allocs anywhere)
__device__ int    g_src[NE];    // int64-fallback only
__device__ int    g_dst[NE];    // int64-fallback only
__device__ __half g_w16[NE];    // fp16 weight cache (6.4MB)
__device__ float  g_deg[NN];
__device__ float  g_dinv[NN];
__device__ __half g_p1[NN];     // half(dinv * x)
__device__ float  g_acc1[NN];
__device__ __half g_gd[NN];     // half(dinv * (g1-g0))
__device__ float  g_acc2[NN];
__device__ unsigned g_hi_or;    // 0 => int64 edge_index

__device__ __forceinline__ int clampn(int v) { return min(max(v, 0), NN - 1); }

// ------------------- node init + tiny dtype probe ---------------------------
__global__ void k_init(const unsigned int* __restrict__ ei32) {
    int n = blockIdx.x * blockDim.x + threadIdx.x;
    if (n == 0) g_hi_or = 0u;
    if (n < NN) {
        g_deg[n]  = 1.0f;   // self-loop weight
        g_acc1[n] = 0.0f;
    }
    if (blockIdx.x == 0) {    // sample 2048 odd words (0 iff int64 high halves)
        unsigned v = 0u;
        #pragma unroll
        for (int k = 0; k < 8; k++) v |= ei32[2 * (threadIdx.x * 8 + k) + 1];
        #pragma unroll
        for (int off = 16; off > 0; off >>= 1)
            v |= __shfl_xor_sync(0xFFFFFFFFu, v, off);
        if ((threadIdx.x & 31) == 0 && v) atomicOr(&g_hi_or, v);
    }
}

// ------- edge: degree REDs + fp16 weight cache (16 edges/thread) ------------
__global__ void k_deg(const void* __restrict__ eiv,
                      const float* __restrict__ w) {
    int e = (blockIdx.x * blockDim.x + threadIdx.x) * 16;
    if (e >= NE) return;
    if (g_hi_or != 0u) {                      // int32 payload
        const int* dp = (const int*)eiv + NE;
        float4 wv[4];
        int4   dv[4];
        #pragma unroll
        for (int q = 0; q < 4; q++) {
            wv[q] = __ldcs((const float4*)(w + e + 4 * q));
            dv[q] = __ldcs((const int4*)(dp + e + 4 * q));
        }
        #pragma unroll
        for (int q = 0; q < 4; q++) {
            __half2 h0 = __floats2half2_rn(wv[q].x, wv[q].y);
            __half2 h1 = __floats2half2_rn(wv[q].z, wv[q].w);
            *(uint2*)(g_w16 + e + 4 * q) =
                make_uint2(*(unsigned*)&h0, *(unsigned*)&h1);
        }
        #pragma unroll
        for (int q = 0; q < 4; q++) {
            atomicAdd(&g_deg[clampn(dv[q].x)], wv[q].x);
            atomicAdd(&g_deg[clampn(dv[q].y)], wv[q].y);
            atomicAdd(&g_deg[clampn(dv[q].z)], wv[q].z);
            atomicAdd(&g_deg[clampn(dv[q].w)], wv[q].w);
        }
    } else {                                  // int64 fallback: narrow + stash
        const long long* ei = (const long long*)eiv;
        #pragma unroll
        for (int k = 0; k < 16; k++) {
            int s = clampn((int)ei[e + k]);
            int d = clampn((int)ei[NE + e + k]);
            float wk = w[e + k];
            g_src[e + k] = s;  g_dst[e + k] = d;
            g_w16[e + k] = __float2half_rn(wk);
            atomicAdd(&g_deg[d], wk);
        }
    }
}

// ---------------------------------------- node: dinv + pre-scaled feature
__global__ void k_dinv(const float* __restrict__ x) {
    int n = blockIdx.x * blockDim.x + threadIdx.x;
    if (n < NN) {
        float d  = g_deg[n];
        float di = (d > 0.0f) ? rsqrtf(d) : 0.0f;
        g_dinv[n] = di;
        g_p1[n]   = __float2half_rn(di * x[n]);
    }
}

// -------- edge: layer-1 aggregation, 16 edges/thread ------------------------
__global__ void k_scatter1(const void* __restrict__ eiv) {
    int e = (blockIdx.x * blockDim.x + threadIdx.x) * 16;
    if (e >= NE) return;
    const int* sp; const int* dp;
    if (g_hi_or != 0u) { sp = (const int*)eiv; dp = sp + NE; }
    else               { sp = g_src;           dp = g_dst;   }
    int4  sv[4], dv[4];
    uint4 wp0 = __ldcs((const uint4*)(g_w16 + e));
    uint4 wp1 = __ldcs((const uint4*)(g_w16 + e + 8));
    #pragma unroll
    for (int q = 0; q < 4; q++) {
        sv[q] = __ldcs((const int4*)(sp + e + 4 * q));
        dv[q] = __ldcs((const int4*)(dp + e + 4 * q));
    }
    float p[16];
    #pragma unroll
    for (int q = 0; q < 4; q++) {
        p[4*q+0] = __half2float(__ldg(&g_p1[clampn(sv[q].x)]));
        p[4*q+1] = __half2float(__ldg(&g_p1[clampn(sv[q].y)]));
        p[4*q+2] = __half2float(__ldg(&g_p1[clampn(sv[q].z)]));
        p[4*q+3] = __half2float(__ldg(&g_p1[clampn(sv[q].w)]));
    }
    float wf[16];
    {
        const unsigned* wr = &wp0.x;
        #pragma unroll
        for (int i = 0; i < 4; i++) {
            float2 f = __half22float2(*(__half2*)&wr[i]);
            wf[2*i] = f.x; wf[2*i+1] = f.y;
        }
        wr = &wp1.x;
        #pragma unroll
        for (int i = 0; i < 4; i++) {
            float2 f = __half22float2(*(__half2*)&wr[i]);
            wf[8+2*i] = f.x; wf[8+2*i+1] = f.y;
        }
    }
    #pragma unroll
    for (int q = 0; q < 4; q++) {
        atomicAdd(&g_acc1[clampn(dv[q].x)], wf[4*q+0] * p[4*q+0]);
        atomicAdd(&g_acc1[clampn(dv[q].y)], wf[4*q+1] * p[4*q+1]);
        atomicAdd(&g_acc1[clampn(dv[q].z)], wf[4*q+2] * p[4*q+2]);
        atomicAdd(&g_acc1[clampn(dv[q].w)], wf[4*q+3] * p[4*q+3]);
    }
}

// -------- node: finish layer-1, dense W1/b1/relu/W2, delta-projection -------
__global__ void k_node_mid(const float* __restrict__ x,
                           const float* __restrict__ W1,
                           const float* __restrict__ b1,
                           const float* __restrict__ W2) {
    int n = blockIdx.x * blockDim.x + threadIdx.x;
    if (n < NN) {
        float di = g_dinv[n];
        float sv = di * (g_acc1[n] + di * x[n]);
        float g0 = 0.0f, g1 = 0.0f;
        #pragma unroll
        for (int j = 0; j < 16; j++) {
            float h = fmaxf(fmaf(sv, __ldg(&W1[j]), __ldg(&b1[j])), 0.0f);
            g0 = fmaf(h, __ldg(&W2[2 * j    ]), g0);
            g1 = fmaf(h, __ldg(&W2[2 * j + 1]), g1);
        }
        float gd = di * (g1 - g0);     // only the class difference matters
        g_gd[n]   = __float2half_rn(gd);
        g_acc2[n] = gd;                // self-loop seed
    }
}

// -------- edge: layer-2 aggregation (scalar), 16 edges/thread ---------------
__global__ void k_scatter2(const void* __restrict__ eiv) {
    int e = (blockIdx.x * blockDim.x + threadIdx.x) * 16;
    if (e >= NE) return;
    const int* sp; const int* dp;
    if (g_hi_or != 0u) { sp = (const int*)eiv; dp = sp + NE; }
    else               { sp = g_src;           dp = g_dst;   }
    int4  sv[4], dv[4];
    uint4 wp0 = __ldcs((const uint4*)(g_w16 + e));
    uint4 wp1 = __ldcs((const uint4*)(g_w16 + e + 8));
    #pragma unroll
    for (int q = 0; q < 4; q++) {
        sv[q] = __ldcs((const int4*)(sp + e + 4 * q));
        dv[q] = __ldcs((const int4*)(dp + e + 4 * q));
    }
    float p[16];
    #pragma unroll
    for (int q = 0; q < 4; q++) {
        p[4*q+0] = __half2float(__ldg(&g_gd[clampn(sv[q].x)]));
        p[4*q+1] = __half2float(__ldg(&g_gd[clampn(sv[q].y)]));
        p[4*q+2] = __half2float(__ldg(&g_gd[clampn(sv[q].z)]));
        p[4*q+3] = __half2float(__ldg(&g_gd[clampn(sv[q].w)]));
    }
    float wf[16];
    {
        const unsigned* wr = &wp0.x;
        #pragma unroll
        for (int i = 0; i < 4; i++) {
            float2 f = __half22float2(*(__half2*)&wr[i]);
            wf[2*i] = f.x; wf[2*i+1] = f.y;
        }
        wr = &wp1.x;
        #pragma unroll
        for (int i = 0; i < 4; i++) {
            float2 f = __half22float2(*(__half2*)&wr[i]);
            wf[8+2*i] = f.x; wf[8+2*i+1] = f.y;
        }
    }
    #pragma unroll
    for (int q = 0; q < 4; q++) {
        atomicAdd(&g_acc2[clampn(dv[q].x)], wf[4*q+0] * p[4*q+0]);
        atomicAdd(&g_acc2[clampn(dv[q].y)], wf[4*q+1] * p[4*q+1]);
        atomicAdd(&g_acc2[clampn(dv[q].z)], wf[4*q+2] * p[4*q+2]);
        atomicAdd(&g_acc2[clampn(dv[q].w)], wf[4*q+3] * p[4*q+3]);
    }
}

// -------------- node: delta -> 2-way log_softmax ----------------------------
__global__ void k_out(const float* __restrict__ b2, float2* __restrict__ out) {
    int n = blockIdx.x * blockDim.x + threadIdx.x;
    if (n < NN) {
        float di = g_dinv[n];
        float v  = di * g_acc2[n] + (__ldg(&b2[1]) - __ldg(&b2[0]));  // v1-v0
        float o0 = (v > 0.0f) ? (-v - log1pf(expf(-v))) : (-log1pf(expf(v)));
        out[n] = make_float2(o0, o0 + v);
    }
}

extern "C" void kernel_launch(void* const* d_in, const int* in_sizes, int n_in,
                              void* d_out, int out_size) {
    const float* x = 0; const void* ei = 0; const float* w = 0;
    const float* W1 = 0; const float* b1 = 0; const float* W2 = 0; const float* b2 = 0;
    for (int i = 0; i < n_in; i++) {
        int sz = in_sizes[i];
        if      (sz == NN)     x  = (const float*)d_in[i];
        else if (sz == 2 * NE) ei = d_in[i];
        else if (sz == NE)     w  = (const float*)d_in[i];
        else if (sz == 32)     W2 = (const float*)d_in[i];
        else if (sz == 2)      b2 = (const float*)d_in[i];
        else if (sz == 16) {
            if (!W1) W1 = (const float*)d_in[i];
            else     b1 = (const float*)d_in[i];
        }
    }

    const int TB = 256;
    const int GN = (NN + TB - 1) / TB;
    const int GE = (NE / 16 + TB - 1) / TB;   // NE % 16 == 0

    k_init      <<<GN, TB>>>((const unsigned int*)ei);
    k_deg       <<<GE, TB>>>(ei, w);
    k_dinv      <<<GN, TB>>>(x);
    k_scatter1  <<<GE, TB>>>(ei);
    k_node_mid  <<<GN, TB>>>(x, W1, b1, W2);
    k_scatter2  <<<GE, TB>>>(ei);
    k_out       <<<GN, TB>>>(b2, (float2*)d_out);
}